// round 2
// baseline (speedup 1.0000x reference)
#include <cuda_runtime.h>
#include <cstdint>

#define Nn   8192
#define Ee   262144
#define Tt   2048
#define NBLK 152
#define NMAT 151
#define NTHR 1024

// ---- scratch (no allocation allowed: device globals) ----
__device__ float g_v[Nn];        // xTB - x
__device__ float g_x1[Nn];       // edge scatter result
__device__ float g_x21[Nn];      // W2@v + b2
__device__ float g_x2[Nn];       // W3@x21 + b3
__device__ float g_h[Tt * 8];    // LSTM hidden states
__device__ int   g_bar1;         // barrier between matvec1 and matvec2
__device__ int   g_done;         // matvec blocks finished

__device__ __forceinline__ float tanhap(float x) {
    float y;
    asm("tanh.approx.f32 %0, %1;" : "=f"(y) : "f"(x));
    return y;
}

// ---------------------------------------------------------------------------
// K0: init — zero scatter buffer + flags, compute v = xTB - x
// ---------------------------------------------------------------------------
__global__ void gl_init(const float* __restrict__ x, const float* __restrict__ xTB) {
    int i = blockIdx.x * blockDim.x + threadIdx.x;
    if (i < Nn) {
        g_v[i]  = xTB[i] - x[i];
        g_x1[i] = 0.f;
    }
    if (i == 0) { g_bar1 = 0; g_done = 0; }
}

// warp-per-row matvec: vout[row] = W[row,:]·vin + b[row]
__device__ __forceinline__ void matvec_rows(const float* __restrict__ W,
                                            const float* __restrict__ vin,
                                            const float* __restrict__ b,
                                            float* __restrict__ vout,
                                            int gw, int nw, int lane) {
    const float4* vv = (const float4*)vin;
    for (int row = gw; row < Nn; row += nw) {
        const float4* wr = (const float4*)(W + (size_t)row * Nn);
        float acc0 = 0.f, acc1 = 0.f;
        #pragma unroll 4
        for (int j = lane; j < Nn / 4; j += 64) {
            float4 w0 = __ldg(wr + j);
            float4 u0 = __ldg(vv + j);
            float4 w1 = __ldg(wr + j + 32);
            float4 u1 = __ldg(vv + j + 32);
            acc0 += w0.x * u0.x + w0.y * u0.y + w0.z * u0.z + w0.w * u0.w;
            acc1 += w1.x * u1.x + w1.y * u1.y + w1.z * u1.z + w1.w * u1.w;
        }
        float acc = acc0 + acc1;
        #pragma unroll
        for (int o = 16; o; o >>= 1) acc += __shfl_down_sync(0xffffffffu, acc, o);
        if (lane == 0) vout[row] = acc + b[row];
    }
}

// ---------------------------------------------------------------------------
// K1: mega kernel.
//   blocks 0..150 : edge scatter, matvec1, barrier, matvec2, signal done
//   block  151    : LSTM recurrence (warp 0, gate-per-lane), W1 dot, combine
// ---------------------------------------------------------------------------
__global__ void __launch_bounds__(NTHR, 1)
gl_main(const float* __restrict__ x,   const float* __restrict__ cur,
        const int*   __restrict__ ei,  const float* __restrict__ att,
        const float* __restrict__ W2,  const float* __restrict__ b2,
        const float* __restrict__ W3,  const float* __restrict__ b3,
        const float* __restrict__ Wih, const float* __restrict__ Whh,
        const float* __restrict__ bih, const float* __restrict__ bhh,
        const float* __restrict__ W1,  const float* __restrict__ b1,
        const float* __restrict__ x30, float* __restrict__ out) {
    __shared__ float s_cur[Tt + 8];
    __shared__ float s_red[NTHR / 32];
    __shared__ float s_x3;

    const int lane = threadIdx.x & 31;
    const int warp = threadIdx.x >> 5;

    if (blockIdx.x < NMAT) {
        // ---------------- matvec / scatter blocks ----------------
        {
            int tid  = blockIdx.x * NTHR + threadIdx.x;
            int nthr = NMAT * NTHR;
            for (int e = tid; e < Ee; e += nthr) {
                int s = ei[e];
                int d = ei[Ee + e];
                float m = (__ldg(x + s) - __ldg(x + d)) * __ldg(att + e);
                atomicAdd(&g_x1[d], m);
            }
        }

        int gw = blockIdx.x * (NTHR / 32) + warp;
        int nw = NMAT * (NTHR / 32);

        matvec_rows(W2, g_v, b2, g_x21, gw, nw, lane);

        // inter-block barrier among the NMAT matvec blocks
        __syncthreads();
        if (threadIdx.x == 0) {
            __threadfence();
            atomicAdd(&g_bar1, 1);
            while (atomicAdd(&g_bar1, 0) < NMAT) {}
            __threadfence();
        }
        __syncthreads();

        matvec_rows(W3, g_x21, b3, g_x2, gw, nw, lane);

        __syncthreads();
        if (threadIdx.x == 0) {
            __threadfence();
            atomicAdd(&g_done, 1);
        }
    } else {
        // ---------------- LSTM block ----------------
        for (int i = threadIdx.x; i < Tt; i += NTHR) s_cur[i] = cur[i];
        if (threadIdx.x < 8) s_cur[Tt + threadIdx.x] = 0.f;
        __syncthreads();

        if (warp == 0) {
            // gate-per-lane layout: lane = gate*8 + unit
            //   gates 0(i),1(f),3(o) are sigmoid: sigmoid(z)=0.5*tanh(z/2)+0.5
            //   gate 2(g) is tanh.
            const int u  = lane & 7;
            const int gt = lane >> 3;
            const bool sig = (gt != 2);
            const float wscale = sig ? 0.5f : 1.0f;
            const float sca = sig ? 0.5f : 1.0f;   // post-tanh scale
            const float scb = sig ? 0.5f : 0.0f;   // post-tanh offset

            float w0 = wscale * Whh[lane * 8 + 0];
            float w1 = wscale * Whh[lane * 8 + 1];
            float w2 = wscale * Whh[lane * 8 + 2];
            float w3 = wscale * Whh[lane * 8 + 3];
            float w4 = wscale * Whh[lane * 8 + 4];
            float w5 = wscale * Whh[lane * 8 + 5];
            float w6 = wscale * Whh[lane * 8 + 6];
            float w7 = wscale * Whh[lane * 8 + 7];
            float a  = wscale * Wih[lane];
            float bb = wscale * (bih[lane] + bhh[lane]);

            float h = 0.f, c = 0.f;
            float* ghp = g_h + u;

            #pragma unroll 2
            for (int t = 0; t < Tt; t++) {
                float xt = s_cur[t];
                // broadcast hidden state (lanes 0..7 hold units 0..7)
                float h0 = __shfl_sync(0xffffffffu, h, 0);
                float h1 = __shfl_sync(0xffffffffu, h, 1);
                float h2 = __shfl_sync(0xffffffffu, h, 2);
                float h3 = __shfl_sync(0xffffffffu, h, 3);
                float h4 = __shfl_sync(0xffffffffu, h, 4);
                float h5 = __shfl_sync(0xffffffffu, h, 5);
                float h6 = __shfl_sync(0xffffffffu, h, 6);
                float h7 = __shfl_sync(0xffffffffu, h, 7);

                float pre = fmaf(a, xt, bb);
                // one 8-long dot per lane, 2 accumulators
                float acc0 = fmaf(w0, h0, pre);
                float acc1 = w1 * h1;
                acc0 = fmaf(w2, h2, acc0);
                acc1 = fmaf(w3, h3, acc1);
                acc0 = fmaf(w4, h4, acc0);
                acc1 = fmaf(w5, h5, acc1);
                acc0 = fmaf(w6, h6, acc0);
                acc1 = fmaf(w7, h7, acc1);
                float z = acc0 + acc1;

                float v = fmaf(tanhap(z), sca, scb);   // gate value for (gt,u)

                // gather the 4 gates of this lane's unit
                float si = __shfl_sync(0xffffffffu, v, u);
                float sf = __shfl_sync(0xffffffffu, v, 8 + u);
                float tg = __shfl_sync(0xffffffffu, v, 16 + u);
                float so = __shfl_sync(0xffffffffu, v, 24 + u);

                c = fmaf(sf, c, si * tg);
                h = so * tanhap(c);

                if (lane < 8) ghp[t * 8] = h;
            }
        }
        __syncthreads();   // g_h visible block-wide

        // x3 scalar = W1 · hs_flat + b1
        float part = 0.f;
        for (int k = threadIdx.x; k < Tt * 8; k += NTHR)
            part = fmaf(__ldg(W1 + k), g_h[k], part);
        #pragma unroll
        for (int o = 16; o; o >>= 1) part += __shfl_down_sync(0xffffffffu, part, o);
        if (lane == 0) s_red[warp] = part;
        __syncthreads();
        if (threadIdx.x == 0) {
            float s = 0.f;
            #pragma unroll
            for (int w = 0; w < NTHR / 32; w++) s += s_red[w];
            s_x3 = s + b1[0];
            while (atomicAdd(&g_done, 0) < NMAT) {}  // wait for matvec/scatter blocks
            __threadfence();
        }
        __syncthreads();

        float x3 = s_x3;
        for (int i = threadIdx.x; i < Nn; i += NTHR)
            out[i] = x[i] + g_x1[i] + g_x2[i] + x3 * x30[i];
    }
}

// ---------------------------------------------------------------------------
extern "C" void kernel_launch(void* const* d_in, const int* in_sizes, int n_in,
                              void* d_out, int out_size) {
    const float* x   = (const float*)d_in[0];
    const float* xTB = (const float*)d_in[1];
    const float* cur = (const float*)d_in[2];
    const int*   ei  = (const int*)  d_in[3];
    const float* att = (const float*)d_in[4];
    const float* W2  = (const float*)d_in[5];
    const float* b2  = (const float*)d_in[6];
    const float* W3  = (const float*)d_in[7];
    const float* b3  = (const float*)d_in[8];
    const float* Wih = (const float*)d_in[9];
    const float* Whh = (const float*)d_in[10];
    const float* bih = (const float*)d_in[11];
    const float* bhh = (const float*)d_in[12];
    const float* W1  = (const float*)d_in[13];
    const float* b1  = (const float*)d_in[14];
    const float* x30 = (const float*)d_in[15];
    float* out = (float*)d_out;

    gl_init<<<(Nn + 255) / 256, 256>>>(x, xTB);
    gl_main<<<NBLK, NTHR>>>(x, cur, ei, att, W2, b2, W3, b3,
                            Wih, Whh, bih, bhh, W1, b1, x30, out);
}

// round 3
// speedup vs baseline: 1.0633x; 1.0633x over previous
#include <cuda_runtime.h>
#include <cstdint>

#define Nn   8192
#define Ee   262144
#define Tt   2048
#define NBLK 152
#define NMAT 151
#define NTHR 1024

// ---- scratch (no allocation allowed: device globals) ----
__device__ float g_v[Nn];        // xTB - x
__device__ float g_x1[Nn];       // edge scatter result
__device__ float g_x21[Nn];      // W2@v + b2
__device__ float g_x2[Nn];       // W3@x21 + b3
__device__ int   g_bar1;         // barrier between matvec1 and matvec2
__device__ int   g_done;         // matvec blocks finished

// dynamic smem layout:
//   matvec blocks: float s_v[8192]                        (32 KB)
//   LSTM block   : float s_cur[2056]; float s_h[16384];
//                  float s_red[32]; float s_x3            (~74 KB)
#define SMEM_BYTES ((2056 + 16384 + 33) * 4)

__device__ __forceinline__ float tanhap(float x) {
    float y;
    asm("tanh.approx.f32 %0, %1;" : "=f"(y) : "f"(x));
    return y;
}

// ---------------------------------------------------------------------------
// K0: init — zero scatter buffer + flags, compute v = xTB - x
// ---------------------------------------------------------------------------
__global__ void gl_init(const float* __restrict__ x, const float* __restrict__ xTB) {
    int i = blockIdx.x * blockDim.x + threadIdx.x;
    if (i < Nn) {
        g_v[i]  = xTB[i] - x[i];
        g_x1[i] = 0.f;
    }
    if (i == 0) { g_bar1 = 0; g_done = 0; }
}

// warp-per-row matvec, input vector staged in smem.
// inner loop: 8-deep front-batched w LDG.128 chunks + LDS.128 v + FMA.
__device__ __forceinline__ void matvec_rows_smem(const float* __restrict__ W,
                                                 const float4* __restrict__ sv,
                                                 const float* __restrict__ b,
                                                 float* __restrict__ vout,
                                                 int gw, int nw, int lane) {
    for (int row = gw; row < Nn; row += nw) {
        const float4* wr = (const float4*)(W + (size_t)row * Nn) + lane;
        float acc0 = 0.f, acc1 = 0.f;
        #pragma unroll 1
        for (int c = 0; c < 8; ++c) {
            float4 w[8];
            #pragma unroll
            for (int k = 0; k < 8; ++k)
                w[k] = __ldg(wr + 32 * (c * 8 + k));      // front-batched, MLP_p1=8
            #pragma unroll
            for (int k = 0; k < 8; ++k) {
                float4 u = sv[lane + 32 * (c * 8 + k)];   // smem, conflict-free
                acc0 = fmaf(w[k].x, u.x, acc0);
                acc1 = fmaf(w[k].y, u.y, acc1);
                acc0 = fmaf(w[k].z, u.z, acc0);
                acc1 = fmaf(w[k].w, u.w, acc1);
            }
        }
        float acc = acc0 + acc1;
        #pragma unroll
        for (int o = 16; o; o >>= 1) acc += __shfl_down_sync(0xffffffffu, acc, o);
        if (lane == 0) vout[row] = acc + b[row];
    }
}

// ---------------------------------------------------------------------------
// K1: mega kernel.
//   blocks 0..150 : edge scatter, matvec1, barrier, matvec2, signal done
//   block  151    : LSTM recurrence (warp 0, gate-per-lane), W1 dot, combine
// ---------------------------------------------------------------------------
__global__ void __launch_bounds__(NTHR, 1)
gl_main(const float* __restrict__ x,   const float* __restrict__ cur,
        const int*   __restrict__ ei,  const float* __restrict__ att,
        const float* __restrict__ W2,  const float* __restrict__ b2,
        const float* __restrict__ W3,  const float* __restrict__ b3,
        const float* __restrict__ Wih, const float* __restrict__ Whh,
        const float* __restrict__ bih, const float* __restrict__ bhh,
        const float* __restrict__ W1,  const float* __restrict__ b1,
        const float* __restrict__ x30, float* __restrict__ out) {
    extern __shared__ float smem[];

    const int lane = threadIdx.x & 31;
    const int warp = threadIdx.x >> 5;

    if (blockIdx.x < NMAT) {
        // ---------------- matvec / scatter blocks ----------------
        float4* sv = (float4*)smem;   // 8192 floats

        // stage v = xTB - x into smem (g_v from gl_init)
        {
            const float4* gv = (const float4*)g_v;
            for (int i = threadIdx.x; i < Nn / 4; i += NTHR) sv[i] = gv[i];
        }

        // edge scatter (overlaps with smem staging; no smem use)
        {
            int tid  = blockIdx.x * NTHR + threadIdx.x;
            int nthr = NMAT * NTHR;
            for (int e = tid; e < Ee; e += nthr) {
                int s = ei[e];
                int d = ei[Ee + e];
                float m = (__ldg(x + s) - __ldg(x + d)) * __ldg(att + e);
                atomicAdd(&g_x1[d], m);
            }
        }
        __syncthreads();

        int gw = blockIdx.x * (NTHR / 32) + warp;
        int nw = NMAT * (NTHR / 32);

        matvec_rows_smem(W2, sv, b2, g_x21, gw, nw, lane);

        // inter-block barrier among the NMAT matvec blocks
        __syncthreads();
        if (threadIdx.x == 0) {
            __threadfence();
            atomicAdd(&g_bar1, 1);
            while (atomicAdd(&g_bar1, 0) < NMAT) {}
            __threadfence();
        }
        __syncthreads();

        // stage x21 into smem
        {
            const float4* gx = (const float4*)g_x21;
            for (int i = threadIdx.x; i < Nn / 4; i += NTHR) sv[i] = gx[i];
        }
        __syncthreads();

        matvec_rows_smem(W3, sv, b3, g_x2, gw, nw, lane);

        __syncthreads();
        if (threadIdx.x == 0) {
            __threadfence();
            atomicAdd(&g_done, 1);
        }
    } else {
        // ---------------- LSTM block ----------------
        float* s_cur = smem;                 // [2056]
        float* s_h   = smem + 2056;          // [16384]
        float* s_red = smem + 2056 + 16384;  // [32]
        float* s_x3  = s_red + 32;

        for (int i = threadIdx.x; i < Tt; i += NTHR) s_cur[i] = cur[i];
        if (threadIdx.x < 8) s_cur[Tt + threadIdx.x] = 0.f;
        __syncthreads();

        if (warp == 0) {
            // gate-per-lane layout: lane = gate*8 + unit
            //   gates 0(i),1(f),3(o) sigmoid via 0.5*tanh(z/2)+0.5; gate 2(g) tanh
            const int u  = lane & 7;
            const int gt = lane >> 3;
            const bool sig = (gt != 2);
            const float wscale = sig ? 0.5f : 1.0f;
            const float sca = sig ? 0.5f : 1.0f;
            const float scb = sig ? 0.5f : 0.0f;

            float w0 = wscale * Whh[lane * 8 + 0];
            float w1 = wscale * Whh[lane * 8 + 1];
            float w2 = wscale * Whh[lane * 8 + 2];
            float w3 = wscale * Whh[lane * 8 + 3];
            float w4 = wscale * Whh[lane * 8 + 4];
            float w5 = wscale * Whh[lane * 8 + 5];
            float w6 = wscale * Whh[lane * 8 + 6];
            float w7 = wscale * Whh[lane * 8 + 7];
            float a  = wscale * Wih[lane];
            float bb = wscale * (bih[lane] + bhh[lane]);

            float h = 0.f, c = 0.f;
            float xt = s_cur[0];
            float* shp = s_h + u;

            #pragma unroll 2
            for (int t = 0; t < Tt; t++) {
                float pre = fmaf(a, xt, bb);
                float xn  = s_cur[t + 1];     // prefetch next input

                float h0 = __shfl_sync(0xffffffffu, h, 0);
                float h1 = __shfl_sync(0xffffffffu, h, 1);
                float h2 = __shfl_sync(0xffffffffu, h, 2);
                float h3 = __shfl_sync(0xffffffffu, h, 3);
                float h4 = __shfl_sync(0xffffffffu, h, 4);
                float h5 = __shfl_sync(0xffffffffu, h, 5);
                float h6 = __shfl_sync(0xffffffffu, h, 6);
                float h7 = __shfl_sync(0xffffffffu, h, 7);

                float acc0 = fmaf(w0, h0, pre);
                float acc1 = w1 * h1;
                acc0 = fmaf(w2, h2, acc0);
                acc1 = fmaf(w3, h3, acc1);
                acc0 = fmaf(w4, h4, acc0);
                acc1 = fmaf(w5, h5, acc1);
                acc0 = fmaf(w6, h6, acc0);
                acc1 = fmaf(w7, h7, acc1);
                float z = acc0 + acc1;

                float v = fmaf(tanhap(z), sca, scb);

                float si = __shfl_sync(0xffffffffu, v, u);
                float sf = __shfl_sync(0xffffffffu, v, 8 + u);
                float tg = __shfl_sync(0xffffffffu, v, 16 + u);
                float so = __shfl_sync(0xffffffffu, v, 24 + u);

                c = fmaf(sf, c, si * tg);
                h = so * tanhap(c);

                if (lane < 8) shp[t * 8] = h;   // STS, cheap
                xt = xn;
            }
        }
        __syncthreads();   // s_h visible block-wide

        // x3 scalar = W1 · hs_flat + b1
        float part = 0.f;
        for (int k = threadIdx.x; k < Tt * 8; k += NTHR)
            part = fmaf(__ldg(W1 + k), s_h[k], part);
        #pragma unroll
        for (int o = 16; o; o >>= 1) part += __shfl_down_sync(0xffffffffu, part, o);
        if (lane == 0) s_red[warp] = part;
        __syncthreads();
        if (threadIdx.x == 0) {
            float s = 0.f;
            #pragma unroll
            for (int w = 0; w < NTHR / 32; w++) s += s_red[w];
            *s_x3 = s + b1[0];
            while (atomicAdd(&g_done, 0) < NMAT) {}  // wait for matvec/scatter
            __threadfence();
        }
        __syncthreads();

        float x3 = *s_x3;
        for (int i = threadIdx.x; i < Nn; i += NTHR)
            out[i] = x[i] + g_x1[i] + g_x2[i] + x3 * x30[i];
    }
}

// ---------------------------------------------------------------------------
extern "C" void kernel_launch(void* const* d_in, const int* in_sizes, int n_in,
                              void* d_out, int out_size) {
    const float* x   = (const float*)d_in[0];
    const float* xTB = (const float*)d_in[1];
    const float* cur = (const float*)d_in[2];
    const int*   ei  = (const int*)  d_in[3];
    const float* att = (const float*)d_in[4];
    const float* W2  = (const float*)d_in[5];
    const float* b2  = (const float*)d_in[6];
    const float* W3  = (const float*)d_in[7];
    const float* b3  = (const float*)d_in[8];
    const float* Wih = (const float*)d_in[9];
    const float* Whh = (const float*)d_in[10];
    const float* bih = (const float*)d_in[11];
    const float* bhh = (const float*)d_in[12];
    const float* W1  = (const float*)d_in[13];
    const float* b1  = (const float*)d_in[14];
    const float* x30 = (const float*)d_in[15];
    float* out = (float*)d_out;

    cudaFuncSetAttribute(gl_main, cudaFuncAttributeMaxDynamicSharedMemorySize,
                         SMEM_BYTES);

    gl_init<<<(Nn + 255) / 256, 256>>>(x, xTB);
    gl_main<<<NBLK, NTHR, SMEM_BYTES>>>(x, cur, ei, att, W2, b2, W3, b3,
                                        Wih, Whh, bih, bhh, W1, b1, x30, out);
}